// round 10
// baseline (speedup 1.0000x reference)
#include <cuda_runtime.h>

#define TT 512
#define BB 256
#define II 64
#define NN 512
#define NB (BB*NN)
#define NBLK 432
#define NGRP 36

__device__ __align__(256) float g_Wc0[576 * NN];
__device__ __align__(256) float g_Wc1[1088 * NN];
__device__ __align__(256) float g_Wc2[1088 * NN];
__device__ __align__(256) float g_bc[3 * NN];
__device__ __align__(256) float g_S[2][3][NB];
__device__ __align__(256) float g_P[NBLK * 8192];
__device__ __align__(256) unsigned g_c1[NGRP * 32];
__device__ __align__(256) unsigned g_cm[32];
__device__ __align__(256) unsigned g_gen[32];
__device__ __align__(256) unsigned g_tc[48 * 32];

__device__ __forceinline__ unsigned long long bcast2(float x) {
    unsigned long long r;
    asm("mov.b64 %0,{%1,%1};" : "=l"(r) : "f"(x));
    return r;
}
__device__ __forceinline__ void fma2(unsigned long long& c, unsigned long long a,
                                     unsigned long long b) {
    asm("fma.rn.f32x2 %0,%1,%2,%0;" : "+l"(c) : "l"(a), "l"(b));
}
__device__ __forceinline__ float2 upk(unsigned long long v) {
    float2 f;
    asm("mov.b64 {%0,%1},%2;" : "=f"(f.x), "=f"(f.y) : "l"(v));
    return f;
}
__device__ __forceinline__ void cpa16(float* s, const float* g) {
    unsigned ss = (unsigned)__cvta_generic_to_shared(s);
    asm volatile("cp.async.cg.shared.global [%0],[%1],16;\n" ::"r"(ss), "l"(g));
}
__device__ __forceinline__ unsigned ldacq(const unsigned* p) {
    unsigned v;
    asm volatile("ld.acquire.gpu.b32 %0,[%1];" : "=r"(v) : "l"(p) : "memory");
    return v;
}

// Tree barrier: 12 blocks -> 36 group counters -> 1 master.
__device__ __forceinline__ void gridbar(unsigned& gen, int grp) {
    __threadfence();
    __syncthreads();
    if (threadIdx.x == 0) {
        unsigned g = gen;
        if (atomicAdd(&g_c1[grp * 32], 1u) == 11u) {
            atomicExch(&g_c1[grp * 32], 0u);
            if (atomicAdd(&g_cm[0], 1u) == NGRP - 1u) {
                atomicExch(&g_cm[0], 0u);
                __threadfence();
                asm volatile("st.release.gpu.b32 [%0],%1;" ::"l"(g_gen), "r"(g + 1u) : "memory");
            } else {
                while (ldacq(g_gen) == g) {}
            }
        } else {
            while (ldacq(g_gen) == g) {}
        }
    }
    gen++;
    __syncthreads();
}

__global__ void __launch_bounds__(128, 3) persist_kernel(
    const float* __restrict__ data, const float* __restrict__ h0,
    const float* __restrict__ Win, const float* __restrict__ b_in,
    const float* __restrict__ Whh, const float* __restrict__ b_hh,
    const float* __restrict__ Whi, const float* __restrict__ b_hi,
    const float* __restrict__ Wfc, const float* __restrict__ bfc,
    float* __restrict__ out) {
    extern __shared__ float sm[];
    float* Asb[2] = {sm, sm + 4608};
    float* Bsb[2] = {sm + 9216, sm + 11264};

    const int tid = threadIdx.x;
    const int jid = blockIdx.x;
    const int grp = jid % NGRP;
    unsigned gen = 0;
    if (tid == 0) gen = *(volatile unsigned*)g_gen;

    // ---- prep ----
    {
        int gt = jid * 128 + tid;
        const int gs = NBLK * 128;
        for (int i = gt; i < 576 * NN; i += gs) {
            int k = i >> 9, n = i & 511;
            g_Wc0[i] = (k < 512) ? ((k == n) ? 0.f : Whh[k * 512 + n])
                                 : Win[(k - 512) * 512 + n];
        }
        for (int i = gt; i < 1088 * NN; i += gs) {
            int k = i >> 9, n = i & 511;
            float v;
            if (k < 512)       v = (k == n) ? 0.f : Whh[(512 + k) * 512 + n];
            else if (k < 1024) v = Whi[(k - 512) * 512 + n];
            else               v = Win[(k - 1024) * 512 + n];
            g_Wc1[i] = v;
        }
        for (int i = gt; i < 1088 * NN; i += gs) {
            int k = i >> 9, n = i & 511;
            float v;
            if (k < 512)       v = (k == n) ? 0.f : Whh[(1024 + k) * 512 + n];
            else if (k < 1024) v = Whi[(512 + (k - 512)) * 512 + n];
            else               v = Win[(k - 1024) * 512 + n];
            g_Wc2[i] = v;
        }
        for (int i = gt; i < 3 * NN; i += gs) {
            int l = i >> 9, n = i & 511;
            float v = b_hh[i] + b_in[n];
            if (l > 0) v += b_hi[(l - 1) * 512 + n];
            g_bc[i] = v;
        }
        for (int i = gt; i < 3 * NB; i += gs) {
            float v = h0[i];
            __stcg(&(&g_S[0][0][0])[i], v);
            __stcg(&(&g_S[1][0][0])[i], v);
        }
        for (int i = gt; i < 48 * 32; i += gs) g_tc[i] = 0u;  // replay determinism
    }
    gridbar(gen, grp);

    // ---- job decode ----
    // heavy: jid<352: l=1,2; 16 tiles (128x64) x 11 splits; chunks 3x10 + 4
    // light: jid in [352,432): l=0; 16 tiles x 5 splits; chunks 4,4,4,3,3
    int l, tile, k0, nck, s, nsp, tc;
    if (jid < 352) {
        l = 1 + jid / 176;
        int r = jid % 176;
        tile = r / 11; s = r % 11;
        k0 = s * 96; nck = (s == 10) ? 4 : 3;
        nsp = 11; tc = (l - 1) * 16 + tile;
    } else {
        int r = jid - 352;
        l = 0; tile = r / 5; s = r % 5;
        k0 = (s < 3) ? s * 128 : 384 + (s - 3) * 96;
        nck = (s < 3) ? 4 : 3;
        nsp = 5; tc = 32 + tile;
    }
    const int row0 = (tile >> 3) * 128, col0 = (tile & 7) * 64;
    const float* Wc = (l == 0) ? g_Wc0 : ((l == 1) ? g_Wc1 : g_Wc2);
    const int dbase = l ? 1024 : 512;
    const int tx = tid & 7, ty = tid >> 3;
    const int base = jid - s;
    const int c4a = (s * 2048) / nsp, c4b = ((s + 1) * 2048) / nsp;
    unsigned tct = 0;

    auto loadB = [&](int ci, int buf) {
        const float* wsrc = Wc + (size_t)(k0 + ci * 32) * NN + col0;
        float* Bd = Bsb[buf];
#pragma unroll
        for (int i = 0; i < 4; i++) {
            int u = i * 128 + tid;
            int r = u >> 4, q = (u & 15) * 4;
            cpa16(&Bd[r * 64 + q], wsrc + (size_t)r * NN + q);
        }
    };

    if (l == 0) { loadB(0, 0); asm volatile("cp.async.commit_group;\n"); }

    for (int kk = 0; kk < TT + 2; kk++) {
        const int cur = kk & 1, prev = cur ^ 1;
        const int t = kk - l;
        if (t >= 0 && t < TT) {
            auto loadA = [&](int ci, int buf) {
                int kabs = k0 + ci * 32;
                const float* src;
                int sA;
                if (kabs < 512)                { src = &g_S[prev][l][kabs];           sA = NN; }
                else if (l > 0 && kabs < 1024) { src = &g_S[prev][l - 1][kabs - 512]; sA = NN; }
                else { src = data + (size_t)t * (BB * II) + (kabs - dbase);           sA = II; }
                src += (size_t)row0 * sA;
                float* Ad = Asb[buf];
#pragma unroll
                for (int i = 0; i < 8; i++) {
                    int u = i * 128 + tid;
                    int r = u >> 3, q = (u & 7) * 4;
                    cpa16(&Ad[r * 36 + q], src + (size_t)r * sA + q);
                }
            };

            unsigned long long acc[8][4];
#pragma unroll
            for (int m = 0; m < 8; m++)
#pragma unroll
                for (int j = 0; j < 4; j++) acc[m][j] = 0ull;

            loadA(0, 0);                       // B0 prefetched pre-barrier
            asm volatile("cp.async.commit_group;\n");
            for (int ci = 0; ci < nck; ci++) {
                int buf = ci & 1;
                if (ci + 1 < nck) {
                    loadA(ci + 1, buf ^ 1);
                    loadB(ci + 1, buf ^ 1);
                    asm volatile("cp.async.commit_group;\n");
                    asm volatile("cp.async.wait_group 1;\n");
                } else {
                    asm volatile("cp.async.wait_group 0;\n");
                }
                __syncthreads();
                const float* A = Asb[buf];
                const float* Bp = Bsb[buf];
#pragma unroll 2
                for (int k = 0; k < 32; k += 2) {
                    const float* Br0 = &Bp[k * 64 + tx * 2];
                    const float* Br1 = &Bp[k * 64 + 64 + tx * 2];
                    unsigned long long B00 = *(const unsigned long long*)&Br0[0];
                    unsigned long long B01 = *(const unsigned long long*)&Br0[16];
                    unsigned long long B02 = *(const unsigned long long*)&Br0[32];
                    unsigned long long B03 = *(const unsigned long long*)&Br0[48];
                    unsigned long long B10 = *(const unsigned long long*)&Br1[0];
                    unsigned long long B11 = *(const unsigned long long*)&Br1[16];
                    unsigned long long B12 = *(const unsigned long long*)&Br1[32];
                    unsigned long long B13 = *(const unsigned long long*)&Br1[48];
#pragma unroll
                    for (int m = 0; m < 8; m++) {
                        float2 a = *(const float2*)&A[(ty + 16 * m) * 36 + k];
                        unsigned long long a0 = bcast2(a.x), a1 = bcast2(a.y);
                        fma2(acc[m][0], a0, B00);
                        fma2(acc[m][1], a0, B01);
                        fma2(acc[m][2], a0, B02);
                        fma2(acc[m][3], a0, B03);
                        fma2(acc[m][0], a1, B10);
                        fma2(acc[m][1], a1, B11);
                        fma2(acc[m][2], a1, B12);
                        fma2(acc[m][3], a1, B13);
                    }
                }
                __syncthreads();
            }

            // publish partial
            {
                float* P = &g_P[(size_t)jid * 8192];
#pragma unroll
                for (int m = 0; m < 8; m++)
#pragma unroll
                    for (int j = 0; j < 4; j++) {
                        float2 v = upk(acc[m][j]);
                        __stcg((float2*)&P[(ty + 16 * m) * 64 + j * 16 + tx * 2], v);
                    }
            }
            __threadfence();
            __syncthreads();
            if (tid == 0) atomicAdd(&g_tc[tc * 32], 1u);
            tct += nsp;
            if (tid == 0) {
                while (ldacq(&g_tc[tc * 32]) < tct) {}
            }
            __syncthreads();

            // distributed combine: this split's float4 slice [c4a, c4b)
            {
                const float* hold = g_S[prev][l];
                float* dst = g_S[cur][l];
                const float* bias = &g_bc[l * NN];
                for (int i4 = c4a + tid; i4 < c4b; i4 += 128) {
                    float4 sv = __ldcg((const float4*)&g_P[(size_t)base * 8192] + i4);
                    for (int sp = 1; sp < nsp; sp++) {
                        float4 p = __ldcg((const float4*)&g_P[(size_t)(base + sp) * 8192] + i4);
                        sv.x += p.x; sv.y += p.y; sv.z += p.z; sv.w += p.w;
                    }
                    int e = i4 * 4;
                    int gr = row0 + (e >> 6), gc = col0 + (e & 63);
                    float4 h = __ldcg((const float4*)&hold[gr * NN + gc]);
                    float4 b = *(const float4*)&bias[gc];
                    float4 o;
                    o.x = 0.5f * h.x + 0.5f * (sv.x + b.x);
                    o.y = 0.5f * h.y + 0.5f * (sv.y + b.y);
                    o.z = 0.5f * h.z + 0.5f * (sv.z + b.z);
                    o.w = 0.5f * h.w + 0.5f * (sv.w + b.w);
                    o.x = (o.x > 0.f) ? o.x : 0.01f * o.x;
                    o.y = (o.y > 0.f) ? o.y : 0.01f * o.y;
                    o.z = (o.z > 0.f) ? o.z : 0.01f * o.z;
                    o.w = (o.w > 0.f) ? o.w : 0.01f * o.w;
                    __stcg((float4*)&dst[gr * NN + gc], o);
                }
            }
        }
        // prefetch next tick's B0 while waiting at the barrier
        int tn = kk + 1 - l;
        if (tn >= 0 && tn < TT) {
            loadB(0, 0);
            asm volatile("cp.async.commit_group;\n");
        }
        gridbar(gen, grp);
    }

    // ---- readout ----
    {
        int warp0 = jid * 4 + (tid >> 5);
        int lane = tid & 31;
        for (int gw = warp0; gw < BB * 10; gw += NBLK * 4) {
            int b = gw / 10, c = gw % 10;
            const float* h = &g_S[1][2][b * NN];
            float sv = 0.f;
            for (int k = lane; k < NN; k += 32)
                sv += __ldcg(&h[k]) * Wfc[k * 10 + c];
#pragma unroll
            for (int o = 16; o; o >>= 1) sv += __shfl_down_sync(0xffffffffu, sv, o);
            if (lane == 0) out[b * 10 + c] = sv + bfc[c];
        }
    }
}

extern "C" void kernel_launch(void* const* d_in, const int* in_sizes, int n_in,
                              void* d_out, int out_size) {
    const float* data = (const float*)d_in[0];
    const float* h0   = (const float*)d_in[1];
    const float* Win  = (const float*)d_in[2];
    const float* b_in = (const float*)d_in[3];
    const float* Whh  = (const float*)d_in[4];
    const float* b_hh = (const float*)d_in[5];
    const float* Whi  = (const float*)d_in[6];
    const float* b_hi = (const float*)d_in[7];
    const float* Wfc  = (const float*)d_in[8];
    const float* b_fc = (const float*)d_in[9];
    float* out = (float*)d_out;

    cudaFuncSetAttribute(persist_kernel, cudaFuncAttributeMaxDynamicSharedMemorySize, 53248);
    persist_kernel<<<NBLK, 128, 53248>>>(data, h0, Win, b_in, Whh, b_hh, Whi, b_hi,
                                         Wfc, b_fc, out);
}

// round 11
// speedup vs baseline: 1.0591x; 1.0591x over previous
#include <cuda_runtime.h>

#define TT 512
#define BB 256
#define II 64
#define NN 512
#define NB (BB*NN)
#define NBLK 288
#define NGRP 36

__device__ __align__(256) float g_Wc0[576 * NN];
__device__ __align__(256) float g_Wc1[1088 * NN];
__device__ __align__(256) float g_Wc2[1088 * NN];
__device__ __align__(256) float g_bc[3 * NN];
__device__ __align__(256) float g_S[2][3][NB];
__device__ __align__(256) float g_P[NBLK * 8192];
__device__ __align__(256) unsigned g_c1[NGRP * 32];
__device__ __align__(256) unsigned g_cm[32];
__device__ __align__(256) unsigned g_gen[32];
__device__ __align__(256) unsigned g_tile[48 * 32];  // publishes per tile
__device__ __align__(256) unsigned g_td[48 * 32];    // combines per tile
__device__ __align__(256) unsigned g_pub[8 * 32];    // publishes per group
__device__ __align__(256) unsigned g_done[8 * 32];   // combines per group

__device__ __forceinline__ unsigned long long bcast2(float x) {
    unsigned long long r;
    asm("mov.b64 %0,{%1,%1};" : "=l"(r) : "f"(x));
    return r;
}
__device__ __forceinline__ void fma2(unsigned long long& c, unsigned long long a,
                                     unsigned long long b) {
    asm("fma.rn.f32x2 %0,%1,%2,%0;" : "+l"(c) : "l"(a), "l"(b));
}
__device__ __forceinline__ float2 upk(unsigned long long v) {
    float2 f;
    asm("mov.b64 {%0,%1},%2;" : "=f"(f.x), "=f"(f.y) : "l"(v));
    return f;
}
__device__ __forceinline__ void cpa16(float* s, const float* g) {
    unsigned ss = (unsigned)__cvta_generic_to_shared(s);
    asm volatile("cp.async.cg.shared.global [%0],[%1],16;\n" ::"r"(ss), "l"(g));
}
__device__ __forceinline__ unsigned ldacq(const unsigned* p) {
    unsigned v;
    asm volatile("ld.acquire.gpu.b32 %0,[%1];" : "=r"(v) : "l"(p) : "memory");
    return v;
}
#define SPIN_GE(addr, tgt) do { while ((int)ldacq(addr) < (int)(tgt)) {} } while (0)

__device__ __forceinline__ void gridbar(unsigned& gen, int grp) {
    __threadfence();
    __syncthreads();
    if (threadIdx.x == 0) {
        unsigned g = gen;
        if (atomicAdd(&g_c1[grp * 32], 1u) == 7u) {
            atomicExch(&g_c1[grp * 32], 0u);
            if (atomicAdd(&g_cm[0], 1u) == NGRP - 1u) {
                atomicExch(&g_cm[0], 0u);
                __threadfence();
                asm volatile("st.release.gpu.b32 [%0],%1;" ::"l"(g_gen), "r"(g + 1u) : "memory");
            } else {
                while (ldacq(g_gen) == g) {}
            }
        } else {
            while (ldacq(g_gen) == g) {}
        }
    }
    gen++;
    __syncthreads();
}

__global__ void __launch_bounds__(128, 2) persist_kernel(
    const float* __restrict__ data, const float* __restrict__ h0,
    const float* __restrict__ Win, const float* __restrict__ b_in,
    const float* __restrict__ Whh, const float* __restrict__ b_hh,
    const float* __restrict__ Whi, const float* __restrict__ b_hi,
    const float* __restrict__ Wfc, const float* __restrict__ bfc,
    float* __restrict__ out) {
    extern __shared__ float sm[];
    float* Asb[2] = {sm, sm + 4608};
    float* Bsb[2] = {sm + 9216, sm + 11264};

    const int tid = threadIdx.x;
    const int jid = blockIdx.x;
    const int grp = jid % NGRP;
    unsigned gen = 0;
    if (tid == 0) gen = *(volatile unsigned*)g_gen;

    // ---- prep ----
    {
        int gt = jid * 128 + tid;
        const int gs = NBLK * 128;
        for (int i = gt; i < 576 * NN; i += gs) {
            int k = i >> 9, n = i & 511;
            g_Wc0[i] = (k < 512) ? ((k == n) ? 0.f : Whh[k * 512 + n])
                                 : Win[(k - 512) * 512 + n];
        }
        for (int i = gt; i < 1088 * NN; i += gs) {
            int k = i >> 9, n = i & 511;
            float v;
            if (k < 512)       v = (k == n) ? 0.f : Whh[(512 + k) * 512 + n];
            else if (k < 1024) v = Whi[(k - 512) * 512 + n];
            else               v = Win[(k - 1024) * 512 + n];
            g_Wc1[i] = v;
        }
        for (int i = gt; i < 1088 * NN; i += gs) {
            int k = i >> 9, n = i & 511;
            float v;
            if (k < 512)       v = (k == n) ? 0.f : Whh[(1024 + k) * 512 + n];
            else if (k < 1024) v = Whi[(512 + (k - 512)) * 512 + n];
            else               v = Win[(k - 1024) * 512 + n];
            g_Wc2[i] = v;
        }
        for (int i = gt; i < 3 * NN; i += gs) {
            int l = i >> 9, n = i & 511;
            float v = b_hh[i] + b_in[n];
            if (l > 0) v += b_hi[(l - 1) * 512 + n];
            g_bc[i] = v;
        }
        for (int i = gt; i < 3 * NB; i += gs) {
            float v = h0[i];
            __stcg(&(&g_S[0][0][0])[i], v);
            __stcg(&(&g_S[1][0][0])[i], v);
        }
        for (int i = gt; i < 48 * 32; i += gs) { g_tile[i] = 0u; g_td[i] = 0u; }
        for (int i = gt; i < 8 * 32; i += gs)  { g_pub[i] = 0u; g_done[i] = 0u; }
    }
    gridbar(gen, grp);

    // ---- job decode (R9 structure) ----
    int l, tile, k0, nck, s, nsp, tc;
    if (jid < 224) {
        l = 1 + jid / 112;
        int r = jid % 112;
        tile = r / 7; s = r % 7;
        k0 = s * 160; nck = (s == 6) ? 4 : 5;
        nsp = 7; tc = (l - 1) * 16 + tile;
    } else {
        int r = jid - 224;
        l = 0; tile = r >> 2; s = r & 3;
        k0 = (s < 2) ? s * 160 : 320 + (s - 2) * 128;
        nck = (s < 2) ? 5 : 4;
        nsp = 4; tc = 32 + tile;
    }
    const int row0 = (tile >> 3) * 128, col0 = (tile & 7) * 64;
    const int rh = tile >> 3;
    const float* Wc = (l == 0) ? g_Wc0 : ((l == 1) ? g_Wc1 : g_Wc2);
    const int dbase = l ? 1024 : 512;
    const int tx = tid & 7, ty = tid >> 3;
    const int base = jid - s;
    const int c4a = (s * 2048) / nsp, c4b = ((s + 1) * 2048) / nsp;

    // dataflow group constants
    const int gid = l * 2 + rh;                       // own group
    const int C = 8 * nsp;                            // jobs/instance own group
    const int gidp = (l > 0) ? (l - 1) * 2 + rh : 0;  // producer group (n_{l-1})
    const int Cp = (l == 1) ? 32 : 56;
    const int gidn = (l < 2) ? (l + 1) * 2 + rh : 0;  // consumer group (WAR)
    const int Cn = 56;
    const bool need_h = (k0 < 512);
    const bool need_n = (l > 0) && (k0 + nck * 32 > 512) && (k0 < 1024);

    auto loadB = [&](int ci, int buf) {
        const float* wsrc = Wc + (size_t)(k0 + ci * 32) * NN + col0;
        float* Bd = Bsb[buf];
#pragma unroll
        for (int i = 0; i < 4; i++) {
            int u = i * 128 + tid;
            int r = u >> 4, q = (u & 15) * 4;
            cpa16(&Bd[r * 64 + q], wsrc + (size_t)r * NN + q);
        }
    };

    // ---- free-running wavefront: each block runs its own 512 steps ----
    for (int t = 0; t < TT; t++) {
        const int kk = t + l;
        const int cur = kk & 1, prev = cur ^ 1;

        // B0 prefetch (weights: no dependency)
        loadB(0, 0);
        asm volatile("cp.async.commit_group;\n");

        // (A) producer waits before touching state segments
        if (tid == 0) {
            if (need_h && t > 0) SPIN_GE(&g_done[gid * 32], t * C);
            if (need_n)          SPIN_GE(&g_done[gidp * 32], (t + 1) * Cp);
        }
        __syncthreads();

        auto loadA = [&](int ci, int buf) {
            int kabs = k0 + ci * 32;
            const float* src;
            int sA;
            if (kabs < 512)                { src = &g_S[prev][l][kabs];           sA = NN; }
            else if (l > 0 && kabs < 1024) { src = &g_S[prev][l - 1][kabs - 512]; sA = NN; }
            else { src = data + (size_t)t * (BB * II) + (kabs - dbase);           sA = II; }
            src += (size_t)row0 * sA;
            float* Ad = Asb[buf];
#pragma unroll
            for (int i = 0; i < 8; i++) {
                int u = i * 128 + tid;
                int r = u >> 3, q = (u & 7) * 4;
                cpa16(&Ad[r * 36 + q], src + (size_t)r * sA + q);
            }
        };

        unsigned long long acc[8][4];
#pragma unroll
        for (int m = 0; m < 8; m++)
#pragma unroll
            for (int j = 0; j < 4; j++) acc[m][j] = 0ull;

        loadA(0, 0);
        asm volatile("cp.async.commit_group;\n");
        for (int ci = 0; ci < nck; ci++) {
            int buf = ci & 1;
            if (ci + 1 < nck) {
                loadA(ci + 1, buf ^ 1);
                loadB(ci + 1, buf ^ 1);
                asm volatile("cp.async.commit_group;\n");
                asm volatile("cp.async.wait_group 1;\n");
            } else {
                asm volatile("cp.async.wait_group 0;\n");
            }
            __syncthreads();
            const float* A = Asb[buf];
            const float* Bp = Bsb[buf];
#pragma unroll 2
            for (int k = 0; k < 32; k += 2) {
                const float* Br0 = &Bp[k * 64 + tx * 2];
                const float* Br1 = &Bp[k * 64 + 64 + tx * 2];
                unsigned long long B00 = *(const unsigned long long*)&Br0[0];
                unsigned long long B01 = *(const unsigned long long*)&Br0[16];
                unsigned long long B02 = *(const unsigned long long*)&Br0[32];
                unsigned long long B03 = *(const unsigned long long*)&Br0[48];
                unsigned long long B10 = *(const unsigned long long*)&Br1[0];
                unsigned long long B11 = *(const unsigned long long*)&Br1[16];
                unsigned long long B12 = *(const unsigned long long*)&Br1[32];
                unsigned long long B13 = *(const unsigned long long*)&Br1[48];
#pragma unroll
                for (int m = 0; m < 8; m++) {
                    float2 a = *(const float2*)&A[(ty + 16 * m) * 36 + k];
                    unsigned long long a0 = bcast2(a.x), a1 = bcast2(a.y);
                    fma2(acc[m][0], a0, B00);
                    fma2(acc[m][1], a0, B01);
                    fma2(acc[m][2], a0, B02);
                    fma2(acc[m][3], a0, B03);
                    fma2(acc[m][0], a1, B10);
                    fma2(acc[m][1], a1, B11);
                    fma2(acc[m][2], a1, B12);
                    fma2(acc[m][3], a1, B13);
                }
            }
            __syncthreads();
        }

        // (B) WAR on g_P: siblings' combines of previous step must be done
        if (tid == 0 && t > 0) SPIN_GE(&g_td[tc * 32], nsp * t);
        __syncthreads();

        // publish partial
        {
            float* P = &g_P[(size_t)jid * 8192];
#pragma unroll
            for (int m = 0; m < 8; m++)
#pragma unroll
                for (int j = 0; j < 4; j++) {
                    float2 v = upk(acc[m][j]);
                    __stcg((float2*)&P[(ty + 16 * m) * 64 + j * 16 + tx * 2], v);
                }
        }
        __threadfence();
        __syncthreads();
        if (tid == 0) {
            atomicAdd(&g_tile[tc * 32], 1u);
            atomicAdd(&g_pub[gid * 32], 1u);
        }

        // (C) all tile publishes; (D) WAR on g_S slot + hold-read readiness
        if (tid == 0) {
            SPIN_GE(&g_tile[tc * 32], nsp * (t + 1));
            if (t > 0) {
                SPIN_GE(&g_done[gid * 32], t * C);   // hold rows ready
                SPIN_GE(&g_pub[gid * 32], t * C);    // own-group readers of t-2 slot done
            }
            if (t > 1 && l < 2) SPIN_GE(&g_pub[gidn * 32], (t - 1) * Cn);
        }
        __syncthreads();

        // distributed combine: slice [c4a, c4b)
        {
            const float* hold = g_S[prev][l];
            float* dst = g_S[cur][l];
            const float* bias = &g_bc[l * NN];
            for (int i4 = c4a + tid; i4 < c4b; i4 += 128) {
                float4 sv = __ldcg((const float4*)&g_P[(size_t)base * 8192] + i4);
                for (int sp = 1; sp < nsp; sp++) {
                    float4 p = __ldcg((const float4*)&g_P[(size_t)(base + sp) * 8192] + i4);
                    sv.x += p.x; sv.y += p.y; sv.z += p.z; sv.w += p.w;
                }
                int e = i4 * 4;
                int gr = row0 + (e >> 6), gc = col0 + (e & 63);
                float4 h = __ldcg((const float4*)&hold[gr * NN + gc]);
                float4 b = *(const float4*)&bias[gc];
                float4 o;
                o.x = 0.5f * h.x + 0.5f * (sv.x + b.x);
                o.y = 0.5f * h.y + 0.5f * (sv.y + b.y);
                o.z = 0.5f * h.z + 0.5f * (sv.z + b.z);
                o.w = 0.5f * h.w + 0.5f * (sv.w + b.w);
                o.x = (o.x > 0.f) ? o.x : 0.01f * o.x;
                o.y = (o.y > 0.f) ? o.y : 0.01f * o.y;
                o.z = (o.z > 0.f) ? o.z : 0.01f * o.z;
                o.w = (o.w > 0.f) ? o.w : 0.01f * o.w;
                __stcg((float4*)&dst[gr * NN + gc], o);
            }
        }
        __threadfence();
        __syncthreads();
        if (tid == 0) {
            atomicAdd(&g_td[tc * 32], 1u);
            atomicAdd(&g_done[gid * 32], 1u);
        }
    }

    gridbar(gen, grp);

    // ---- readout ----
    {
        int warp0 = jid * 4 + (tid >> 5);
        int lane = tid & 31;
        for (int gw = warp0; gw < BB * 10; gw += NBLK * 4) {
            int b = gw / 10, c = gw % 10;
            const float* h = &g_S[1][2][b * NN];
            float sv = 0.f;
            for (int k = lane; k < NN; k += 32)
                sv += __ldcg(&h[k]) * Wfc[k * 10 + c];
#pragma unroll
            for (int o = 16; o; o >>= 1) sv += __shfl_down_sync(0xffffffffu, sv, o);
            if (lane == 0) out[b * 10 + c] = sv + bfc[c];
        }
    }
}

extern "C" void kernel_launch(void* const* d_in, const int* in_sizes, int n_in,
                              void* d_out, int out_size) {
    const float* data = (const float*)d_in[0];
    const float* h0   = (const float*)d_in[1];
    const float* Win  = (const float*)d_in[2];
    const float* b_in = (const float*)d_in[3];
    const float* Whh  = (const float*)d_in[4];
    const float* b_hh = (const float*)d_in[5];
    const float* Whi  = (const float*)d_in[6];
    const float* b_hi = (const float*)d_in[7];
    const float* Wfc  = (const float*)d_in[8];
    const float* b_fc = (const float*)d_in[9];
    float* out = (float*)d_out;

    cudaFuncSetAttribute(persist_kernel, cudaFuncAttributeMaxDynamicSharedMemorySize, 53248);
    persist_kernel<<<NBLK, 128, 53248>>>(data, h0, Win, b_in, Whh, b_hh, Whi, b_hi,
                                         Wfc, b_fc, out);
}